// round 4
// baseline (speedup 1.0000x reference)
#include <cuda_runtime.h>
#include <math.h>

#define B_    2
#define S_    2048
#define HID   2048
#define HQ    16
#define HKV   4
#define D_    128
#define MROWS (B_ * S_)      // 4096
#define KVW   (HKV * D_)     // 512

// ---------------- scratch (allocation-free: __device__ globals) ----------------
__device__ float g_qproj[(size_t)MROWS * HID];
__device__ float g_kproj[(size_t)MROWS * KVW];
__device__ float g_vproj[(size_t)MROWS * KVW];
__device__ float g_gate [(size_t)MROWS * HID];
__device__ float g_q[(size_t)B_ * HQ  * S_ * D_];   // [b][h][s][d]
__device__ float g_k[(size_t)B_ * HKV * S_ * D_];
__device__ float g_v[(size_t)B_ * HKV * S_ * D_];
__device__ float g_attn[(size_t)MROWS * HID];       // gated attention output [m][h*D+d]

// ---------------- SGEMM: C[m][n] = sum_k A[m][k] * B[n][k]  (both K-major) ----------------
// 128x128 tile, BK=16, 256 threads, 8x8 per thread.
__global__ void __launch_bounds__(256) sgemm_nt(const float* __restrict__ A,
                                                const float* __restrict__ B,
                                                float* __restrict__ C,
                                                int M, int N, int K)
{
    __shared__ float As[16][132];
    __shared__ float Bs[16][132];
    const int bm = blockIdx.y * 128;
    const int bn = blockIdx.x * 128;
    const int tid = threadIdx.x;
    const int tx = tid & 15, ty = tid >> 4;

    float acc[8][8];
#pragma unroll
    for (int i = 0; i < 8; ++i)
#pragma unroll
        for (int j = 0; j < 8; ++j) acc[i][j] = 0.f;

    const int lr = tid >> 2;            // 0..63
    const int lk = (tid & 3) << 2;      // 0,4,8,12
    const float* Ab = A + (size_t)(bm + lr) * K + lk;
    const float* Bb = B + (size_t)(bn + lr) * K + lk;

    for (int k0 = 0; k0 < K; k0 += 16) {
#pragma unroll
        for (int it = 0; it < 2; ++it) {
            float4 va = *(const float4*)(Ab + (size_t)(it * 64) * K + k0);
            As[lk + 0][lr + it * 64] = va.x;
            As[lk + 1][lr + it * 64] = va.y;
            As[lk + 2][lr + it * 64] = va.z;
            As[lk + 3][lr + it * 64] = va.w;
            float4 vb = *(const float4*)(Bb + (size_t)(it * 64) * K + k0);
            Bs[lk + 0][lr + it * 64] = vb.x;
            Bs[lk + 1][lr + it * 64] = vb.y;
            Bs[lk + 2][lr + it * 64] = vb.z;
            Bs[lk + 3][lr + it * 64] = vb.w;
        }
        __syncthreads();
#pragma unroll
        for (int k = 0; k < 16; ++k) {
            float a[8], b[8];
            *(float4*)&a[0] = *(const float4*)&As[k][ty * 8];
            *(float4*)&a[4] = *(const float4*)&As[k][ty * 8 + 4];
            *(float4*)&b[0] = *(const float4*)&Bs[k][tx * 8];
            *(float4*)&b[4] = *(const float4*)&Bs[k][tx * 8 + 4];
#pragma unroll
            for (int i = 0; i < 8; ++i)
#pragma unroll
                for (int j = 0; j < 8; ++j) acc[i][j] += a[i] * b[j];
        }
        __syncthreads();
    }

#pragma unroll
    for (int i = 0; i < 8; ++i) {
        float* Crow = C + (size_t)(bm + ty * 8 + i) * N + bn + tx * 8;
        *(float4*)(Crow + 0) = make_float4(acc[i][0], acc[i][1], acc[i][2], acc[i][3]);
        *(float4*)(Crow + 4) = make_float4(acc[i][4], acc[i][5], acc[i][6], acc[i][7]);
    }
}

// ---------------- fused RMSNorm + RoPE + layout transpose ----------------
// One warp per 128-dim vector. Lane t owns d = {t, t+32, t+64, t+96}.
__global__ void __launch_bounds__(256) rope_norm_kernel(const float* __restrict__ cosT,
                                                        const float* __restrict__ sinT,
                                                        const float* __restrict__ qw,
                                                        const float* __restrict__ kw)
{
    const int gw   = (blockIdx.x * blockDim.x + threadIdx.x) >> 5;
    const int lane = threadIdx.x & 31;
    const int NQ = MROWS * HQ;    // 65536 q vectors
    const int NK = MROWS * HKV;   // 16384 k (and v) vectors

    if (gw < NQ + NK) {
        bool isq = (gw < NQ);
        int idx = isq ? gw : gw - NQ;
        int nh  = isq ? HQ : HKV;
        int h = idx % nh;
        int m = idx / nh;
        int s = m % S_, b = m / S_;
        const float* x = (isq ? g_qproj + (size_t)m * HID : g_kproj + (size_t)m * KVW) + h * D_;
        const float* w = isq ? qw : kw;

        float x0 = x[lane], x1 = x[lane + 32], x2 = x[lane + 64], x3 = x[lane + 96];
        float ss = x0 * x0 + x1 * x1 + x2 * x2 + x3 * x3;
#pragma unroll
        for (int off = 16; off; off >>= 1) ss += __shfl_xor_sync(0xffffffffu, ss, off);
        float r = rsqrtf(ss * (1.f / 128.f) + 1e-6f);
        x0 = x0 * r * w[lane];
        x1 = x1 * r * w[lane + 32];
        x2 = x2 * r * w[lane + 64];
        x3 = x3 * r * w[lane + 96];

        const float* c  = cosT + (size_t)s * D_;
        const float* sn = sinT + (size_t)s * D_;
        // rotate_half: rot[d] = -x[d+64] (d<64), x[d-64] (d>=64)
        float o0 = x0 * c[lane]      - x2 * sn[lane];
        float o1 = x1 * c[lane + 32] - x3 * sn[lane + 32];
        float o2 = x2 * c[lane + 64] + x0 * sn[lane + 64];
        float o3 = x3 * c[lane + 96] + x1 * sn[lane + 96];

        float* o = (isq ? g_q + (size_t)((b * HQ + h) * S_ + s) * D_
                        : g_k + (size_t)((b * HKV + h) * S_ + s) * D_);
        o[lane] = o0; o[lane + 32] = o1; o[lane + 64] = o2; o[lane + 96] = o3;
    } else if (gw < NQ + 2 * NK) {
        int vi = gw - NQ - NK;
        int h = vi % HKV;
        int m = vi / HKV;
        int s = m % S_, b = m / S_;
        const float* x = g_vproj + (size_t)m * KVW + h * D_;
        float* o = g_v + (size_t)((b * HKV + h) * S_ + s) * D_;
        o[lane] = x[lane]; o[lane + 32] = x[lane + 32];
        o[lane + 64] = x[lane + 64]; o[lane + 96] = x[lane + 96];
    }
}

// ---------------- flash attention (causal) + sigmoid-gate fused epilogue ----------------
// 64x64 tiles, 256 threads (16x16). Rows owned: ty+16i (i<4). Score cols: tx+16j (j<4).
// O cols owned: tx*8+j (j<8). Smem padded: stride 132 for Q/K/V, 65 for P.
#define TSTR 132
#define PSTR 65
#define ATTN_SMEM ((3 * 64 * TSTR + 64 * PSTR) * (int)sizeof(float))

__global__ void __launch_bounds__(256) attn_kernel(const float* __restrict__ gate)
{
    extern __shared__ float sm[];
    float* Qs = sm;
    float* Ks = Qs + 64 * TSTR;
    float* Vs = Ks + 64 * TSTR;
    float* Ps = Vs + 64 * TSTR;

    const int tid = threadIdx.x;
    const int tx = tid & 15, ty = tid >> 4;
    const int bh = blockIdx.y;                 // 0..31
    const int b = bh >> 4, h = bh & 15;
    const int kvh = h >> 2;                    // n_rep = 4
    const int qt = gridDim.x - 1 - blockIdx.x; // heavy tiles scheduled first
    const int q0 = qt * 64;

    const float* Qg = g_q + ((size_t)(b * HQ + h) * S_ + q0) * D_;
    const float* Kg = g_k + (size_t)(b * HKV + kvh) * S_ * D_;
    const float* Vg = g_v + (size_t)(b * HKV + kvh) * S_ * D_;

    for (int idx = tid; idx < 64 * 32; idx += 256) {
        int r = idx >> 5, dq = (idx & 31) << 2;
        *(float4*)(Qs + r * TSTR + dq) = *(const float4*)(Qg + (size_t)r * D_ + dq);
    }

    float mi[4], li[4], O[4][8];
#pragma unroll
    for (int i = 0; i < 4; ++i) {
        mi[i] = -1e30f; li[i] = 0.f;
#pragma unroll
        for (int j = 0; j < 8; ++j) O[i][j] = 0.f;
    }
    const float scale = 0.08838834764831845f;  // 1/sqrt(128)

    for (int k0 = 0; k0 <= q0; k0 += 64) {
        __syncthreads();
        for (int idx = tid; idx < 64 * 32; idx += 256) {
            int r = idx >> 5, dq = (idx & 31) << 2;
            *(float4*)(Ks + r * TSTR + dq) = *(const float4*)(Kg + (size_t)(k0 + r) * D_ + dq);
            *(float4*)(Vs + r * TSTR + dq) = *(const float4*)(Vg + (size_t)(k0 + r) * D_ + dq);
        }
        __syncthreads();

        // scores: rows ty+16i vs cols tx+16j
        float s4[4][4];
#pragma unroll
        for (int i = 0; i < 4; ++i)
#pragma unroll
            for (int j = 0; j < 4; ++j) s4[i][j] = 0.f;

        for (int d = 0; d < D_; d += 4) {
            float4 qa[4], kb[4];
#pragma unroll
            for (int i = 0; i < 4; ++i) qa[i] = *(const float4*)(Qs + (ty + 16 * i) * TSTR + d);
#pragma unroll
            for (int j = 0; j < 4; ++j) kb[j] = *(const float4*)(Ks + (tx + 16 * j) * TSTR + d);
#pragma unroll
            for (int i = 0; i < 4; ++i)
#pragma unroll
                for (int j = 0; j < 4; ++j)
                    s4[i][j] += qa[i].x * kb[j].x + qa[i].y * kb[j].y
                              + qa[i].z * kb[j].z + qa[i].w * kb[j].w;
        }

        const bool diag = (k0 == q0);
#pragma unroll
        for (int i = 0; i < 4; ++i)
#pragma unroll
            for (int j = 0; j < 4; ++j) {
                float v = s4[i][j] * scale;
                if (diag && (tx + 16 * j) > (ty + 16 * i)) v = -1e30f;
                s4[i][j] = v;
            }

        // online softmax, per-row reduce over the 16 lanes sharing ty
#pragma unroll
        for (int i = 0; i < 4; ++i) {
            float rm = fmaxf(fmaxf(s4[i][0], s4[i][1]), fmaxf(s4[i][2], s4[i][3]));
#pragma unroll
            for (int off = 1; off < 16; off <<= 1)
                rm = fmaxf(rm, __shfl_xor_sync(0xffffffffu, rm, off));
            float mnew = fmaxf(mi[i], rm);
            float corr = __expf(mi[i] - mnew);
            float rs = 0.f;
#pragma unroll
            for (int j = 0; j < 4; ++j) {
                float p = __expf(s4[i][j] - mnew);
                s4[i][j] = p;
                rs += p;
            }
#pragma unroll
            for (int off = 1; off < 16; off <<= 1)
                rs += __shfl_xor_sync(0xffffffffu, rs, off);
            li[i] = li[i] * corr + rs;
            mi[i] = mnew;
#pragma unroll
            for (int j = 0; j < 8; ++j) O[i][j] *= corr;
#pragma unroll
            for (int j = 0; j < 4; ++j)
                Ps[(ty + 16 * i) * PSTR + tx + 16 * j] = s4[i][j];
        }
        __syncthreads();

        // PV: O[i][c] += P[row_i][n] * V[n][c],  c = tx*8 + j
#pragma unroll 2
        for (int n = 0; n < 64; ++n) {
            float a0 = Ps[(ty     ) * PSTR + n];
            float a1 = Ps[(ty + 16) * PSTR + n];
            float a2 = Ps[(ty + 32) * PSTR + n];
            float a3 = Ps[(ty + 48) * PSTR + n];
            float4 v0 = *(const float4*)(Vs + n * TSTR + tx * 8);
            float4 v1 = *(const float4*)(Vs + n * TSTR + tx * 8 + 4);
            float vb[8] = {v0.x, v0.y, v0.z, v0.w, v1.x, v1.y, v1.z, v1.w};
#pragma unroll
            for (int j = 0; j < 8; ++j) {
                O[0][j] += a0 * vb[j];
                O[1][j] += a1 * vb[j];
                O[2][j] += a2 * vb[j];
                O[3][j] += a3 * vb[j];
            }
        }
    }

    // epilogue: normalize, multiply by sigmoid(gate), store to [m][h*D + c]
#pragma unroll
    for (int i = 0; i < 4; ++i) {
        int row = q0 + ty + 16 * i;
        size_t m = (size_t)b * S_ + row;
        float inv = 1.f / li[i];
        const float* gr = gate + m * HID + h * D_ + tx * 8;
        float* orow = g_attn + m * HID + h * D_ + tx * 8;
#pragma unroll
        for (int j = 0; j < 8; ++j) {
            float gv = gr[j];
            float sig = 1.f / (1.f + __expf(-gv));
            orow[j] = O[i][j] * inv * sig;
        }
    }
}

// ---------------- launch ----------------
extern "C" void kernel_launch(void* const* d_in, const int* in_sizes, int n_in,
                              void* d_out, int out_size)
{
    const float* hs   = (const float*)d_in[0];
    const float* cosT = (const float*)d_in[1];
    const float* sinT = (const float*)d_in[2];
    const float* Wq   = (const float*)d_in[3];
    const float* Wk   = (const float*)d_in[4];
    const float* Wv   = (const float*)d_in[5];
    const float* Wg   = (const float*)d_in[6];
    const float* Wo   = (const float*)d_in[7];
    const float* qw   = (const float*)d_in[8];
    const float* kw   = (const float*)d_in[9];
    float* out = (float*)d_out;

    float *qp, *kp, *vp, *gp, *ab;
    cudaGetSymbolAddress((void**)&qp, g_qproj);
    cudaGetSymbolAddress((void**)&kp, g_kproj);
    cudaGetSymbolAddress((void**)&vp, g_vproj);
    cudaGetSymbolAddress((void**)&gp, g_gate);
    cudaGetSymbolAddress((void**)&ab, g_attn);

    // projections: hs[4096,2048] @ W[n,2048]^T
    sgemm_nt<<<dim3(HID / 128, MROWS / 128), 256>>>(hs, Wq, qp, MROWS, HID, HID);
    sgemm_nt<<<dim3(KVW / 128, MROWS / 128), 256>>>(hs, Wk, kp, MROWS, KVW, HID);
    sgemm_nt<<<dim3(KVW / 128, MROWS / 128), 256>>>(hs, Wv, vp, MROWS, KVW, HID);
    sgemm_nt<<<dim3(HID / 128, MROWS / 128), 256>>>(hs, Wg, gp, MROWS, HID, HID);

    // RMSNorm + RoPE + transpose to [b][h][s][d]; v transpose only
    {
        int total_warps = MROWS * (HQ + 2 * HKV);   // 98304
        int blocks = total_warps / 8;               // 256 threads = 8 warps
        rope_norm_kernel<<<blocks, 256>>>(cosT, sinT, qw, kw);
    }

    // causal flash attention + gated epilogue
    cudaFuncSetAttribute(attn_kernel, cudaFuncAttributeMaxDynamicSharedMemorySize, ATTN_SMEM);
    attn_kernel<<<dim3(S_ / 64, B_ * HQ), 256, ATTN_SMEM>>>(gp);

    // output projection: gated_attn[4096,2048] @ Wo[2048,2048]^T
    sgemm_nt<<<dim3(HID / 128, MROWS / 128), 256>>>(ab, Wo, out, MROWS, HID, HID);
}

// round 6
// speedup vs baseline: 1.6011x; 1.6011x over previous
#include <cuda_runtime.h>
#include <cuda_bf16.h>
#include <math.h>
#include <cstdint>

#define B_    2
#define S_    2048
#define HID   2048
#define HQ    16
#define HKV   4
#define D_    128
#define MROWS (B_ * S_)      // 4096
#define KVW   (HKV * D_)     // 512

// ---------------- scratch (allocation-free: __device__ globals) ----------------
__device__ float g_qproj[(size_t)MROWS * HID];
__device__ float g_kproj[(size_t)MROWS * KVW];
__device__ float g_vproj[(size_t)MROWS * KVW];
__device__ float g_gate [(size_t)MROWS * HID];
__device__ float g_q[(size_t)B_ * HQ  * S_ * D_];   // [b][h][s][d]
__device__ float g_k[(size_t)B_ * HKV * S_ * D_];
__device__ float g_v[(size_t)B_ * HKV * S_ * D_];

// bf16 hi/lo splits (x = hi + lo; A*B ~= Ahi*Bhi + Ahi*Blo + Alo*Bhi)
__device__ __nv_bfloat16 g_hs_hi[(size_t)MROWS * HID];
__device__ __nv_bfloat16 g_hs_lo[(size_t)MROWS * HID];
__device__ __nv_bfloat16 g_wq_hi[(size_t)HID * HID];
__device__ __nv_bfloat16 g_wq_lo[(size_t)HID * HID];
__device__ __nv_bfloat16 g_wk_hi[(size_t)KVW * HID];
__device__ __nv_bfloat16 g_wk_lo[(size_t)KVW * HID];
__device__ __nv_bfloat16 g_wv_hi[(size_t)KVW * HID];
__device__ __nv_bfloat16 g_wv_lo[(size_t)KVW * HID];
__device__ __nv_bfloat16 g_wg_hi[(size_t)HID * HID];
__device__ __nv_bfloat16 g_wg_lo[(size_t)HID * HID];
__device__ __nv_bfloat16 g_wo_hi[(size_t)HID * HID];
__device__ __nv_bfloat16 g_wo_lo[(size_t)HID * HID];
__device__ __nv_bfloat16 g_at_hi[(size_t)MROWS * HID];
__device__ __nv_bfloat16 g_at_lo[(size_t)MROWS * HID];

// ---------------- PTX helpers (all base-sm_100-safe: cp.async / ldmatrix / mma.sync) ----------------
__device__ __forceinline__ uint32_t smem_u32(const void* p) {
    return (uint32_t)__cvta_generic_to_shared(p);
}
#define CP16(dst, src) \
    asm volatile("cp.async.cg.shared.global [%0], [%1], 16;\n" :: "r"(dst), "l"(src))
#define CP_COMMIT() asm volatile("cp.async.commit_group;\n" ::: "memory")
#define CP_WAIT(n)  asm volatile("cp.async.wait_group %0;\n" :: "n"(n) : "memory")

#define LDMX4(r, addr) \
    asm volatile("ldmatrix.sync.aligned.m8n8.x4.shared.b16 {%0,%1,%2,%3}, [%4];" \
        : "=r"((r)[0]), "=r"((r)[1]), "=r"((r)[2]), "=r"((r)[3]) : "r"(addr))

#define MMA16816(d, a, b) \
    asm volatile("mma.sync.aligned.m16n8k16.row.col.f32.bf16.bf16.f32 " \
        "{%0,%1,%2,%3}, {%4,%5,%6,%7}, {%8,%9}, {%0,%1,%2,%3};" \
        : "+f"((d)[0]), "+f"((d)[1]), "+f"((d)[2]), "+f"((d)[3]) \
        : "r"((a)[0]), "r"((a)[1]), "r"((a)[2]), "r"((a)[3]), "r"((b)[0]), "r"((b)[1]))

// ---------------- split: fp32 -> (bf16 hi, bf16 lo) ----------------
__global__ void __launch_bounds__(256) split_bf16(const float* __restrict__ x,
                                                  __nv_bfloat16* __restrict__ hi,
                                                  __nv_bfloat16* __restrict__ lo, int n)
{
    int i = (blockIdx.x * blockDim.x + threadIdx.x) * 4;
    if (i >= n) return;
    float4 v = *(const float4*)(x + i);
    __nv_bfloat16 h0 = __float2bfloat16(v.x), h1 = __float2bfloat16(v.y);
    __nv_bfloat16 h2 = __float2bfloat16(v.z), h3 = __float2bfloat16(v.w);
    __nv_bfloat16 l0 = __float2bfloat16(v.x - __bfloat162float(h0));
    __nv_bfloat16 l1 = __float2bfloat16(v.y - __bfloat162float(h1));
    __nv_bfloat16 l2 = __float2bfloat16(v.z - __bfloat162float(h2));
    __nv_bfloat16 l3 = __float2bfloat16(v.w - __bfloat162float(h3));
    *(__nv_bfloat162*)(hi + i)     = __nv_bfloat162(h0, h1);
    *(__nv_bfloat162*)(hi + i + 2) = __nv_bfloat162(h2, h3);
    *(__nv_bfloat162*)(lo + i)     = __nv_bfloat162(l0, l1);
    *(__nv_bfloat162*)(lo + i + 2) = __nv_bfloat162(l2, l3);
}

// ---------------- mma.sync bf16x3 GEMM: C[m][n] = sum_k A[m][k]*B[n][k] ----------------
// 128x128 CTA tile, BK=32, 256 threads (warps: 4 in M x 2 in N, warp tile 32x64).
// Smem rows padded to 80B -> conflict-free ldmatrix. cp.async double buffer.
#define BK     32
#define ROWB   80                   // 64B data + 16B pad
#define OPB    (128 * ROWB)         // one operand tile: 10240 B
#define STG    (4 * OPB)            // Ahi, Alo, Bhi, Blo: 40960 B
#define GEMM_SMEM (2 * STG)         // 81920 B

__global__ void __launch_bounds__(256)
gemm_bf16x3(const __nv_bfloat16* __restrict__ Ahi, const __nv_bfloat16* __restrict__ Alo,
            const __nv_bfloat16* __restrict__ Bhi, const __nv_bfloat16* __restrict__ Blo,
            float* __restrict__ C, int N, int K)
{
    extern __shared__ char smem[];
    const uint32_t sb = smem_u32(smem);
    const int tid  = threadIdx.x;
    const int wid  = tid >> 5, lane = tid & 31;
    const int wm   = wid & 3;          // 4 warps in M: 32 rows each
    const int wn   = wid >> 2;         // 2 warps in N: 64 cols each
    const int bm = blockIdx.y * 128, bn = blockIdx.x * 128;

    // ldmatrix per-lane address terms
    const uint32_t a_off = (uint32_t)((lane & 15) * ROWB + (lane >> 4) * 16);
    const uint32_t b_off = (uint32_t)((lane & 7) * ROWB + ((lane >> 4) & 1) * (8 * ROWB)
                                      + ((lane >> 3) & 1) * 16);

    float acc[2][8][4];
#pragma unroll
    for (int i = 0; i < 2; ++i)
#pragma unroll
        for (int j = 0; j < 8; ++j)
#pragma unroll
            for (int v = 0; v < 4; ++v) acc[i][j][v] = 0.f;

    const int T = K / BK;

    // fill stage s with K-tile kt: 4 operands x 128 rows x 4 16B-chunks = 2048 chunks
#define FILL(s, kt) do {                                                          \
        uint32_t base = sb + (uint32_t)(s) * STG;                                 \
        int k0 = (kt) * BK;                                                       \
        _Pragma("unroll")                                                         \
        for (int c = 0; c < 2; ++c) {                                             \
            int chunk = c * 256 + tid;                                            \
            int r = chunk >> 2, o16 = (chunk & 3) * 16;                           \
            uint32_t so = (uint32_t)(r * ROWB + o16);                             \
            const char* pah = (const char*)(Ahi + (size_t)(bm + r) * K + k0) + o16; \
            const char* pal = (const char*)(Alo + (size_t)(bm + r) * K + k0) + o16; \
            const char* pbh = (const char*)(Bhi + (size_t)(bn + r) * K + k0) + o16; \
            const char* pbl = (const char*)(Blo + (size_t)(bn + r) * K + k0) + o16; \
            CP16(base + so,           pah);                                       \
            CP16(base + OPB + so,     pal);                                       \
            CP16(base + 2 * OPB + so, pbh);                                       \
            CP16(base + 3 * OPB + so, pbl);                                       \
        }                                                                         \
    } while (0)

    FILL(0, 0); CP_COMMIT();

    for (int t = 0; t < T; ++t) {
        const int s = t & 1;
        if (t + 1 < T) { FILL(s ^ 1, t + 1); CP_COMMIT(); CP_WAIT(1); }
        else           { CP_WAIT(0); }
        __syncthreads();

        const uint32_t abase = sb + (uint32_t)s * STG + (uint32_t)(wm * 32) * ROWB;
        const uint32_t bbase = sb + (uint32_t)s * STG + 2 * OPB + (uint32_t)(wn * 64) * ROWB;

#pragma unroll
        for (int ks = 0; ks < 2; ++ks) {
            uint32_t ah[2][4], al[2][4];
#pragma unroll
            for (int mi = 0; mi < 2; ++mi) {
                uint32_t aa = abase + (uint32_t)(mi * 16) * ROWB + a_off + ks * 32;
                LDMX4(ah[mi], aa);
                LDMX4(al[mi], aa + OPB);
            }
#pragma unroll
            for (int p = 0; p < 4; ++p) {   // p covers two n8 tiles (2p, 2p+1)
                uint32_t bh[4], bl[4];
                uint32_t ba = bbase + (uint32_t)(p * 16) * ROWB + b_off + ks * 32;
                LDMX4(bh, ba);
                LDMX4(bl, ba + OPB);
#pragma unroll
                for (int mi = 0; mi < 2; ++mi) {
                    MMA16816(acc[mi][2 * p],     ah[mi], bh);
                    MMA16816(acc[mi][2 * p + 1], ah[mi], bh + 2);
                    MMA16816(acc[mi][2 * p],     ah[mi], bl);
                    MMA16816(acc[mi][2 * p + 1], ah[mi], bl + 2);
                    MMA16816(acc[mi][2 * p],     al[mi], bh);
                    MMA16816(acc[mi][2 * p + 1], al[mi], bh + 2);
                }
            }
        }
        __syncthreads();
    }

    // epilogue: c0,c1 -> (row, col..col+1); c2,c3 -> (row+8, col..col+1)
    const int r0 = bm + wm * 32 + (lane >> 2);
    const int c0 = bn + wn * 64 + (lane & 3) * 2;
#pragma unroll
    for (int mi = 0; mi < 2; ++mi)
#pragma unroll
        for (int ni = 0; ni < 8; ++ni) {
            int row = r0 + mi * 16;
            int col = c0 + ni * 8;
            *(float2*)(C + (size_t)row * N + col)       = make_float2(acc[mi][ni][0], acc[mi][ni][1]);
            *(float2*)(C + (size_t)(row + 8) * N + col) = make_float2(acc[mi][ni][2], acc[mi][ni][3]);
        }
#undef FILL
}

// ---------------- fused RMSNorm + RoPE + layout transpose ----------------
__global__ void __launch_bounds__(256) rope_norm_kernel(const float* __restrict__ cosT,
                                                        const float* __restrict__ sinT,
                                                        const float* __restrict__ qw,
                                                        const float* __restrict__ kw)
{
    const int gw   = (blockIdx.x * blockDim.x + threadIdx.x) >> 5;
    const int lane = threadIdx.x & 31;
    const int NQ = MROWS * HQ;
    const int NK = MROWS * HKV;

    if (gw < NQ + NK) {
        bool isq = (gw < NQ);
        int idx = isq ? gw : gw - NQ;
        int nh  = isq ? HQ : HKV;
        int h = idx % nh;
        int m = idx / nh;
        int s = m % S_, b = m / S_;
        const float* x = (isq ? g_qproj + (size_t)m * HID : g_kproj + (size_t)m * KVW) + h * D_;
        const float* w = isq ? qw : kw;

        float x0 = x[lane], x1 = x[lane + 32], x2 = x[lane + 64], x3 = x[lane + 96];
        float ss = x0 * x0 + x1 * x1 + x2 * x2 + x3 * x3;
#pragma unroll
        for (int off = 16; off; off >>= 1) ss += __shfl_xor_sync(0xffffffffu, ss, off);
        float r = rsqrtf(ss * (1.f / 128.f) + 1e-6f);
        x0 = x0 * r * w[lane];
        x1 = x1 * r * w[lane + 32];
        x2 = x2 * r * w[lane + 64];
        x3 = x3 * r * w[lane + 96];

        const float* c  = cosT + (size_t)s * D_;
        const float* sn = sinT + (size_t)s * D_;
        float o0 = x0 * c[lane]      - x2 * sn[lane];
        float o1 = x1 * c[lane + 32] - x3 * sn[lane + 32];
        float o2 = x2 * c[lane + 64] + x0 * sn[lane + 64];
        float o3 = x3 * c[lane + 96] + x1 * sn[lane + 96];

        float* o = (isq ? g_q + (size_t)((b * HQ + h) * S_ + s) * D_
                        : g_k + (size_t)((b * HKV + h) * S_ + s) * D_);
        o[lane] = o0; o[lane + 32] = o1; o[lane + 64] = o2; o[lane + 96] = o3;
    } else if (gw < NQ + 2 * NK) {
        int vi = gw - NQ - NK;
        int h = vi % HKV;
        int m = vi / HKV;
        int s = m % S_, b = m / S_;
        const float* x = g_vproj + (size_t)m * KVW + h * D_;
        float* o = g_v + (size_t)((b * HKV + h) * S_ + s) * D_;
        o[lane] = x[lane]; o[lane + 32] = x[lane + 32];
        o[lane + 64] = x[lane + 64]; o[lane + 96] = x[lane + 96];
    }
}

// ---------------- flash attention (causal) + sigmoid-gate + bf16 split epilogue ----------------
#define TSTR 132
#define PSTR 65
#define ATTN_SMEM ((3 * 64 * TSTR + 64 * PSTR) * (int)sizeof(float))

__global__ void __launch_bounds__(256) attn_kernel(const float* __restrict__ gate)
{
    extern __shared__ float sm[];
    float* Qs = sm;
    float* Ks = Qs + 64 * TSTR;
    float* Vs = Ks + 64 * TSTR;
    float* Ps = Vs + 64 * TSTR;

    const int tid = threadIdx.x;
    const int tx = tid & 15, ty = tid >> 4;
    const int bh = blockIdx.y;
    const int b = bh >> 4, h = bh & 15;
    const int kvh = h >> 2;
    const int qt = gridDim.x - 1 - blockIdx.x;
    const int q0 = qt * 64;

    const float* Qg = g_q + ((size_t)(b * HQ + h) * S_ + q0) * D_;
    const float* Kg = g_k + (size_t)(b * HKV + kvh) * S_ * D_;
    const float* Vg = g_v + (size_t)(b * HKV + kvh) * S_ * D_;

    for (int idx = tid; idx < 64 * 32; idx += 256) {
        int r = idx >> 5, dq = (idx & 31) << 2;
        *(float4*)(Qs + r * TSTR + dq) = *(const float4*)(Qg + (size_t)r * D_ + dq);
    }

    float mi[4], li[4], O[4][8];
#pragma unroll
    for (int i = 0; i < 4; ++i) {
        mi[i] = -1e30f; li[i] = 0.f;
#pragma unroll
        for (int j = 0; j < 8; ++j) O[i][j] = 0.f;
    }
    const float scale = 0.08838834764831845f;

    for (int k0 = 0; k0 <= q0; k0 += 64) {
        __syncthreads();
        for (int idx = tid; idx < 64 * 32; idx += 256) {
            int r = idx >> 5, dq = (idx & 31) << 2;
            *(float4*)(Ks + r * TSTR + dq) = *(const float4*)(Kg + (size_t)(k0 + r) * D_ + dq);
            *(float4*)(Vs + r * TSTR + dq) = *(const float4*)(Vg + (size_t)(k0 + r) * D_ + dq);
        }
        __syncthreads();

        float s4[4][4];
#pragma unroll
        for (int i = 0; i < 4; ++i)
#pragma unroll
            for (int j = 0; j < 4; ++j) s4[i][j] = 0.f;

        for (int d = 0; d < D_; d += 4) {
            float4 qa[4], kb[4];
#pragma unroll
            for (int i = 0; i < 4; ++i) qa[i] = *(const float4*)(Qs + (ty + 16 * i) * TSTR + d);
#pragma unroll
            for (int j = 0; j < 4; ++j) kb[j] = *(const float4*)(Ks + (tx + 16 * j) * TSTR + d);
#pragma unroll
            for (int i = 0; i < 4; ++i)
#pragma unroll
                for (int j = 0; j < 4; ++j)
                    s4[i][j] += qa[i].x * kb[j].x + qa[i].y * kb[j].y
                              + qa[i].z * kb[j].z + qa[i].w * kb[j].w;
        }

        const bool diag = (k0 == q0);
#pragma unroll
        for (int i = 0; i < 4; ++i)
#pragma unroll
            for (int j = 0; j < 4; ++j) {
                float v = s4[i][j] * scale;
                if (diag && (tx + 16 * j) > (ty + 16 * i)) v = -1e30f;
                s4[i][j] = v;
            }

#pragma unroll
        for (int i = 0; i < 4; ++i) {
            float rm = fmaxf(fmaxf(s4[i][0], s4[i][1]), fmaxf(s4[i][2], s4[i][3]));
#pragma unroll
            for (int off = 1; off < 16; off <<= 1)
                rm = fmaxf(rm, __shfl_xor_sync(0xffffffffu, rm, off));
            float mnew = fmaxf(mi[i], rm);
            float corr = __expf(mi[i] - mnew);
            float rs = 0.f;
#pragma unroll
            for (int j = 0; j < 4; ++j) {
                float p = __expf(s4[i][j] - mnew);
                s4[i][j] = p;
                rs += p;
            }
#pragma unroll
            for (int off = 1; off < 16; off <<= 1)
                rs += __shfl_xor_sync(0xffffffffu, rs, off);
            li[i] = li[i] * corr + rs;
            mi[i] = mnew;
#pragma unroll
            for (int j = 0; j < 8; ++j) O[i][j] *= corr;
#pragma unroll
            for (int j = 0; j < 4; ++j)
                Ps[(ty + 16 * i) * PSTR + tx + 16 * j] = s4[i][j];
        }
        __syncthreads();

#pragma unroll 2
        for (int n = 0; n < 64; ++n) {
            float a0 = Ps[(ty     ) * PSTR + n];
            float a1 = Ps[(ty + 16) * PSTR + n];
            float a2 = Ps[(ty + 32) * PSTR + n];
            float a3 = Ps[(ty + 48) * PSTR + n];
            float4 v0 = *(const float4*)(Vs + n * TSTR + tx * 8);
            float4 v1 = *(const float4*)(Vs + n * TSTR + tx * 8 + 4);
            float vb[8] = {v0.x, v0.y, v0.z, v0.w, v1.x, v1.y, v1.z, v1.w};
#pragma unroll
            for (int j = 0; j < 8; ++j) {
                O[0][j] += a0 * vb[j];
                O[1][j] += a1 * vb[j];
                O[2][j] += a2 * vb[j];
                O[3][j] += a3 * vb[j];
            }
        }
    }

    // epilogue: normalize, gate by sigmoid, write bf16 hi/lo split for the Wo GEMM
#pragma unroll
    for (int i = 0; i < 4; ++i) {
        int row = q0 + ty + 16 * i;
        size_t m = (size_t)b * S_ + row;
        float inv = 1.f / li[i];
        const float* gr = gate + m * HID + h * D_ + tx * 8;
        __nv_bfloat16* oh = g_at_hi + m * HID + h * D_ + tx * 8;
        __nv_bfloat16* ol = g_at_lo + m * HID + h * D_ + tx * 8;
#pragma unroll
        for (int j = 0; j < 8; ++j) {
            float gv = gr[j];
            float sig = 1.f / (1.f + __expf(-gv));
            float val = O[i][j] * inv * sig;
            __nv_bfloat16 hv = __float2bfloat16(val);
            oh[j] = hv;
            ol[j] = __float2bfloat16(val - __bfloat162float(hv));
        }
    }
}

// ---------------- launch ----------------
extern "C" void kernel_launch(void* const* d_in, const int* in_sizes, int n_in,
                              void* d_out, int out_size)
{
    const float* hs   = (const float*)d_in[0];
    const float* cosT = (const float*)d_in[1];
    const float* sinT = (const float*)d_in[2];
    const float* Wq   = (const float*)d_in[3];
    const float* Wk   = (const float*)d_in[4];
    const float* Wv   = (const float*)d_in[5];
    const float* Wg   = (const float*)d_in[6];
    const float* Wo   = (const float*)d_in[7];
    const float* qw   = (const float*)d_in[8];
    const float* kw   = (const float*)d_in[9];
    float* out = (float*)d_out;

    float *qp, *kp, *vp, *gp;
    cudaGetSymbolAddress((void**)&qp, g_qproj);
    cudaGetSymbolAddress((void**)&kp, g_kproj);
    cudaGetSymbolAddress((void**)&vp, g_vproj);
    cudaGetSymbolAddress((void**)&gp, g_gate);

    __nv_bfloat16 *hsh, *hsl, *wqh, *wql, *wkh, *wkl, *wvh, *wvl, *wgh, *wgl, *woh, *wol, *ath, *atl;
    cudaGetSymbolAddress((void**)&hsh, g_hs_hi); cudaGetSymbolAddress((void**)&hsl, g_hs_lo);
    cudaGetSymbolAddress((void**)&wqh, g_wq_hi); cudaGetSymbolAddress((void**)&wql, g_wq_lo);
    cudaGetSymbolAddress((void**)&wkh, g_wk_hi); cudaGetSymbolAddress((void**)&wkl, g_wk_lo);
    cudaGetSymbolAddress((void**)&wvh, g_wv_hi); cudaGetSymbolAddress((void**)&wvl, g_wv_lo);
    cudaGetSymbolAddress((void**)&wgh, g_wg_hi); cudaGetSymbolAddress((void**)&wgl, g_wg_lo);
    cudaGetSymbolAddress((void**)&woh, g_wo_hi); cudaGetSymbolAddress((void**)&wol, g_wo_lo);
    cudaGetSymbolAddress((void**)&ath, g_at_hi); cudaGetSymbolAddress((void**)&atl, g_at_lo);

    cudaFuncSetAttribute(gemm_bf16x3, cudaFuncAttributeMaxDynamicSharedMemorySize, GEMM_SMEM);
    cudaFuncSetAttribute(attn_kernel, cudaFuncAttributeMaxDynamicSharedMemorySize, ATTN_SMEM);

    // fp32 -> bf16 hi/lo splits
    const int nHS = MROWS * HID, nSq = HID * HID, nKv = KVW * HID;
    split_bf16<<<nHS / 1024, 256>>>(hs, hsh, hsl, nHS);
    split_bf16<<<nSq / 1024, 256>>>(Wq, wqh, wql, nSq);
    split_bf16<<<nKv / 1024, 256>>>(Wk, wkh, wkl, nKv);
    split_bf16<<<nKv / 1024, 256>>>(Wv, wvh, wvl, nKv);
    split_bf16<<<nSq / 1024, 256>>>(Wg, wgh, wgl, nSq);
    split_bf16<<<nSq / 1024, 256>>>(Wo, woh, wol, nSq);

    // projections on tensor cores (bf16x3, fp32 accumulate)
    gemm_bf16x3<<<dim3(HID / 128, MROWS / 128), 256, GEMM_SMEM>>>(hsh, hsl, wqh, wql, qp, HID, HID);
    gemm_bf16x3<<<dim3(KVW / 128, MROWS / 128), 256, GEMM_SMEM>>>(hsh, hsl, wkh, wkl, kp, KVW, HID);
    gemm_bf16x3<<<dim3(KVW / 128, MROWS / 128), 256, GEMM_SMEM>>>(hsh, hsl, wvh, wvl, vp, KVW, HID);
    gemm_bf16x3<<<dim3(HID / 128, MROWS / 128), 256, GEMM_SMEM>>>(hsh, hsl, wgh, wgl, gp, HID, HID);

    // RMSNorm + RoPE + transpose
    {
        int total_warps = MROWS * (HQ + 2 * HKV);
        rope_norm_kernel<<<total_warps / 8, 256>>>(cosT, sinT, qw, kw);
    }

    // causal flash attention + gated epilogue (writes bf16 hi/lo directly)
    attn_kernel<<<dim3(S_ / 64, B_ * HQ), 256, ATTN_SMEM>>>(gp);

    // output projection on tensor cores
    gemm_bf16x3<<<dim3(HID / 128, MROWS / 128), 256, GEMM_SMEM>>>(ath, atl, woh, wol, out, HID, HID);
}

// round 7
// speedup vs baseline: 2.7880x; 1.7413x over previous
#include <cuda_runtime.h>
#include <cuda_bf16.h>
#include <math.h>
#include <cstdint>

#define B_    2
#define S_    2048
#define HID   2048
#define HQ    16
#define HKV   4
#define D_    128
#define MROWS (B_ * S_)      // 4096
#define KVW   (HKV * D_)     // 512

// ---------------- scratch (allocation-free: __device__ globals) ----------------
__device__ float g_qproj[(size_t)MROWS * HID];
__device__ float g_kproj[(size_t)MROWS * KVW];
__device__ float g_vproj[(size_t)MROWS * KVW];
__device__ float g_gate [(size_t)MROWS * HID];

// q/k/v in bf16 hi/lo, [b][h][s][d]
__device__ __nv_bfloat16 g_qh[(size_t)B_ * HQ  * S_ * D_];
__device__ __nv_bfloat16 g_ql[(size_t)B_ * HQ  * S_ * D_];
__device__ __nv_bfloat16 g_kh[(size_t)B_ * HKV * S_ * D_];
__device__ __nv_bfloat16 g_kl[(size_t)B_ * HKV * S_ * D_];
__device__ __nv_bfloat16 g_vh[(size_t)B_ * HKV * S_ * D_];
__device__ __nv_bfloat16 g_vl[(size_t)B_ * HKV * S_ * D_];

// bf16 hi/lo splits for GEMMs
__device__ __nv_bfloat16 g_hs_hi[(size_t)MROWS * HID];
__device__ __nv_bfloat16 g_hs_lo[(size_t)MROWS * HID];
__device__ __nv_bfloat16 g_wq_hi[(size_t)HID * HID];
__device__ __nv_bfloat16 g_wq_lo[(size_t)HID * HID];
__device__ __nv_bfloat16 g_wk_hi[(size_t)KVW * HID];
__device__ __nv_bfloat16 g_wk_lo[(size_t)KVW * HID];
__device__ __nv_bfloat16 g_wv_hi[(size_t)KVW * HID];
__device__ __nv_bfloat16 g_wv_lo[(size_t)KVW * HID];
__device__ __nv_bfloat16 g_wg_hi[(size_t)HID * HID];
__device__ __nv_bfloat16 g_wg_lo[(size_t)HID * HID];
__device__ __nv_bfloat16 g_wo_hi[(size_t)HID * HID];
__device__ __nv_bfloat16 g_wo_lo[(size_t)HID * HID];
__device__ __nv_bfloat16 g_at_hi[(size_t)MROWS * HID];
__device__ __nv_bfloat16 g_at_lo[(size_t)MROWS * HID];

// ---------------- PTX helpers (base sm_100-safe) ----------------
__device__ __forceinline__ uint32_t smem_u32(const void* p) {
    return (uint32_t)__cvta_generic_to_shared(p);
}
#define CP16(dst, src) \
    asm volatile("cp.async.cg.shared.global [%0], [%1], 16;\n" :: "r"(dst), "l"(src))
#define CP_COMMIT() asm volatile("cp.async.commit_group;\n" ::: "memory")
#define CP_WAIT(n)  asm volatile("cp.async.wait_group %0;\n" :: "n"(n) : "memory")

#define LDMX4(r, addr) \
    asm volatile("ldmatrix.sync.aligned.m8n8.x4.shared.b16 {%0,%1,%2,%3}, [%4];" \
        : "=r"((r)[0]), "=r"((r)[1]), "=r"((r)[2]), "=r"((r)[3]) : "r"(addr))
#define LDMX4T(r, addr) \
    asm volatile("ldmatrix.sync.aligned.m8n8.x4.trans.shared.b16 {%0,%1,%2,%3}, [%4];" \
        : "=r"((r)[0]), "=r"((r)[1]), "=r"((r)[2]), "=r"((r)[3]) : "r"(addr))

#define MMA16816(d, a, b) \
    asm volatile("mma.sync.aligned.m16n8k16.row.col.f32.bf16.bf16.f32 " \
        "{%0,%1,%2,%3}, {%4,%5,%6,%7}, {%8,%9}, {%0,%1,%2,%3};" \
        : "+f"((d)[0]), "+f"((d)[1]), "+f"((d)[2]), "+f"((d)[3]) \
        : "r"((a)[0]), "r"((a)[1]), "r"((a)[2]), "r"((a)[3]), "r"((b)[0]), "r"((b)[1]))

__device__ __forceinline__ float fexp2(float x) {
    float y; asm("ex2.approx.ftz.f32 %0, %1;" : "=f"(y) : "f"(x)); return y;
}

// ---------------- split: fp32 -> (bf16 hi, bf16 lo) ----------------
__global__ void __launch_bounds__(256) split_bf16(const float* __restrict__ x,
                                                  __nv_bfloat16* __restrict__ hi,
                                                  __nv_bfloat16* __restrict__ lo, int n)
{
    int i = (blockIdx.x * blockDim.x + threadIdx.x) * 4;
    if (i >= n) return;
    float4 v = *(const float4*)(x + i);
    __nv_bfloat16 h0 = __float2bfloat16(v.x), h1 = __float2bfloat16(v.y);
    __nv_bfloat16 h2 = __float2bfloat16(v.z), h3 = __float2bfloat16(v.w);
    __nv_bfloat16 l0 = __float2bfloat16(v.x - __bfloat162float(h0));
    __nv_bfloat16 l1 = __float2bfloat16(v.y - __bfloat162float(h1));
    __nv_bfloat16 l2 = __float2bfloat16(v.z - __bfloat162float(h2));
    __nv_bfloat16 l3 = __float2bfloat16(v.w - __bfloat162float(h3));
    *(__nv_bfloat162*)(hi + i)     = __nv_bfloat162(h0, h1);
    *(__nv_bfloat162*)(hi + i + 2) = __nv_bfloat162(h2, h3);
    *(__nv_bfloat162*)(lo + i)     = __nv_bfloat162(l0, l1);
    *(__nv_bfloat162*)(lo + i + 2) = __nv_bfloat162(l2, l3);
}

// ---------------- mma.sync bf16x3 GEMM (unchanged from R5, proven) ----------------
#define BK     32
#define ROWB   80
#define OPB    (128 * ROWB)
#define STG    (4 * OPB)
#define GEMM_SMEM (2 * STG)

__global__ void __launch_bounds__(256)
gemm_bf16x3(const __nv_bfloat16* __restrict__ Ahi, const __nv_bfloat16* __restrict__ Alo,
            const __nv_bfloat16* __restrict__ Bhi, const __nv_bfloat16* __restrict__ Blo,
            float* __restrict__ C, int N, int K)
{
    extern __shared__ char smem[];
    const uint32_t sb = smem_u32(smem);
    const int tid  = threadIdx.x;
    const int wid  = tid >> 5, lane = tid & 31;
    const int wm   = wid & 3;
    const int wn   = wid >> 2;
    const int bm = blockIdx.y * 128, bn = blockIdx.x * 128;

    const uint32_t a_off = (uint32_t)((lane & 15) * ROWB + (lane >> 4) * 16);
    const uint32_t b_off = (uint32_t)((lane & 7) * ROWB + ((lane >> 4) & 1) * (8 * ROWB)
                                      + ((lane >> 3) & 1) * 16);

    float acc[2][8][4];
#pragma unroll
    for (int i = 0; i < 2; ++i)
#pragma unroll
        for (int j = 0; j < 8; ++j)
#pragma unroll
            for (int v = 0; v < 4; ++v) acc[i][j][v] = 0.f;

    const int T = K / BK;

#define FILL(s, kt) do {                                                          \
        uint32_t base = sb + (uint32_t)(s) * STG;                                 \
        int k0 = (kt) * BK;                                                       \
        _Pragma("unroll")                                                         \
        for (int c = 0; c < 2; ++c) {                                             \
            int chunk = c * 256 + tid;                                            \
            int r = chunk >> 2, o16 = (chunk & 3) * 16;                           \
            uint32_t so = (uint32_t)(r * ROWB + o16);                             \
            const char* pah = (const char*)(Ahi + (size_t)(bm + r) * K + k0) + o16; \
            const char* pal = (const char*)(Alo + (size_t)(bm + r) * K + k0) + o16; \
            const char* pbh = (const char*)(Bhi + (size_t)(bn + r) * K + k0) + o16; \
            const char* pbl = (const char*)(Blo + (size_t)(bn + r) * K + k0) + o16; \
            CP16(base + so,           pah);                                       \
            CP16(base + OPB + so,     pal);                                       \
            CP16(base + 2 * OPB + so, pbh);                                       \
            CP16(base + 3 * OPB + so, pbl);                                       \
        }                                                                         \
    } while (0)

    FILL(0, 0); CP_COMMIT();

    for (int t = 0; t < T; ++t) {
        const int s = t & 1;
        if (t + 1 < T) { FILL(s ^ 1, t + 1); CP_COMMIT(); CP_WAIT(1); }
        else           { CP_WAIT(0); }
        __syncthreads();

        const uint32_t abase = sb + (uint32_t)s * STG + (uint32_t)(wm * 32) * ROWB;
        const uint32_t bbase = sb + (uint32_t)s * STG + 2 * OPB + (uint32_t)(wn * 64) * ROWB;

#pragma unroll
        for (int ks = 0; ks < 2; ++ks) {
            uint32_t ah[2][4], al[2][4];
#pragma unroll
            for (int mi = 0; mi < 2; ++mi) {
                uint32_t aa = abase + (uint32_t)(mi * 16) * ROWB + a_off + ks * 32;
                LDMX4(ah[mi], aa);
                LDMX4(al[mi], aa + OPB);
            }
#pragma unroll
            for (int p = 0; p < 4; ++p) {
                uint32_t bh[4], bl[4];
                uint32_t ba = bbase + (uint32_t)(p * 16) * ROWB + b_off + ks * 32;
                LDMX4(bh, ba);
                LDMX4(bl, ba + OPB);
#pragma unroll
                for (int mi = 0; mi < 2; ++mi) {
                    MMA16816(acc[mi][2 * p],     ah[mi], bh);
                    MMA16816(acc[mi][2 * p + 1], ah[mi], bh + 2);
                    MMA16816(acc[mi][2 * p],     ah[mi], bl);
                    MMA16816(acc[mi][2 * p + 1], ah[mi], bl + 2);
                    MMA16816(acc[mi][2 * p],     al[mi], bh);
                    MMA16816(acc[mi][2 * p + 1], al[mi], bh + 2);
                }
            }
        }
        __syncthreads();
    }

    const int r0 = bm + wm * 32 + (lane >> 2);
    const int c0 = bn + wn * 64 + (lane & 3) * 2;
#pragma unroll
    for (int mi = 0; mi < 2; ++mi)
#pragma unroll
        for (int ni = 0; ni < 8; ++ni) {
            int row = r0 + mi * 16;
            int col = c0 + ni * 8;
            *(float2*)(C + (size_t)row * N + col)       = make_float2(acc[mi][ni][0], acc[mi][ni][1]);
            *(float2*)(C + (size_t)(row + 8) * N + col) = make_float2(acc[mi][ni][2], acc[mi][ni][3]);
        }
#undef FILL
}

// ---------------- fused RMSNorm + RoPE + transpose -> bf16 hi/lo ----------------
__device__ __forceinline__ void st_hilo(__nv_bfloat16* ph, __nv_bfloat16* pl, float v) {
    __nv_bfloat16 h = __float2bfloat16(v);
    *ph = h;
    *pl = __float2bfloat16(v - __bfloat162float(h));
}

__global__ void __launch_bounds__(256) rope_norm_kernel(const float* __restrict__ cosT,
                                                        const float* __restrict__ sinT,
                                                        const float* __restrict__ qw,
                                                        const float* __restrict__ kw)
{
    const int gw   = (blockIdx.x * blockDim.x + threadIdx.x) >> 5;
    const int lane = threadIdx.x & 31;
    const int NQ = MROWS * HQ;
    const int NK = MROWS * HKV;

    if (gw < NQ + NK) {
        bool isq = (gw < NQ);
        int idx = isq ? gw : gw - NQ;
        int nh  = isq ? HQ : HKV;
        int h = idx % nh;
        int m = idx / nh;
        int s = m % S_, b = m / S_;
        const float* x = (isq ? g_qproj + (size_t)m * HID : g_kproj + (size_t)m * KVW) + h * D_;
        const float* w = isq ? qw : kw;

        float x0 = x[lane], x1 = x[lane + 32], x2 = x[lane + 64], x3 = x[lane + 96];
        float ss = x0 * x0 + x1 * x1 + x2 * x2 + x3 * x3;
#pragma unroll
        for (int off = 16; off; off >>= 1) ss += __shfl_xor_sync(0xffffffffu, ss, off);
        float r = rsqrtf(ss * (1.f / 128.f) + 1e-6f);
        x0 = x0 * r * w[lane];
        x1 = x1 * r * w[lane + 32];
        x2 = x2 * r * w[lane + 64];
        x3 = x3 * r * w[lane + 96];

        const float* c  = cosT + (size_t)s * D_;
        const float* sn = sinT + (size_t)s * D_;
        float o0 = x0 * c[lane]      - x2 * sn[lane];
        float o1 = x1 * c[lane + 32] - x3 * sn[lane + 32];
        float o2 = x2 * c[lane + 64] + x0 * sn[lane + 64];
        float o3 = x3 * c[lane + 96] + x1 * sn[lane + 96];

        size_t base = isq ? (size_t)((b * HQ + h) * S_ + s) * D_
                          : (size_t)((b * HKV + h) * S_ + s) * D_;
        __nv_bfloat16* oh = isq ? g_qh + base : g_kh + base;
        __nv_bfloat16* ol = isq ? g_ql + base : g_kl + base;
        st_hilo(oh + lane,      ol + lane,      o0);
        st_hilo(oh + lane + 32, ol + lane + 32, o1);
        st_hilo(oh + lane + 64, ol + lane + 64, o2);
        st_hilo(oh + lane + 96, ol + lane + 96, o3);
    } else if (gw < NQ + 2 * NK) {
        int vi = gw - NQ - NK;
        int h = vi % HKV;
        int m = vi / HKV;
        int s = m % S_, b = m / S_;
        const float* x = g_vproj + (size_t)m * KVW + h * D_;
        size_t base = (size_t)((b * HKV + h) * S_ + s) * D_;
        st_hilo(g_vh + base + lane,      g_vl + base + lane,      x[lane]);
        st_hilo(g_vh + base + lane + 32, g_vl + base + lane + 32, x[lane + 32]);
        st_hilo(g_vh + base + lane + 64, g_vl + base + lane + 64, x[lane + 64]);
        st_hilo(g_vh + base + lane + 96, g_vl + base + lane + 96, x[lane + 96]);
    }
}

// ---------------- tensor-core flash attention (causal, bf16x3) ----------------
// CTA: 128 q-rows x 64-wide KV tiles, 8 warps (16 q-rows each, full KV width).
// Smem: Q hi/lo resident; K/V hi/lo double-buffered. Row stride 272B (17x16B, odd).
#define QR    128
#define KT    64
#define DSTR  272
#define QARR  (QR * DSTR)        // 34816 (one Q array)
#define KARR  (KT * DSTR)        // 17408 (one K or V array)
#define KVSTG (4 * KARR)         // 69632 per stage (Kh,Kl,Vh,Vl)
#define ATTN_SMEM (2 * QARR + 2 * KVSTG)   // 208896

__global__ void __launch_bounds__(256) attn_tc(const float* __restrict__ gate)
{
    extern __shared__ char smc[];
    const uint32_t sb = smem_u32(smc);
    const int tid = threadIdx.x;
    const int wid = tid >> 5, lane = tid & 31;
    const int bh = blockIdx.y;
    const int b = bh >> 4, h = bh & 15;
    const int kvh = h >> 2;
    const int qt = gridDim.x - 1 - blockIdx.x;   // heavy tiles first
    const int q0 = qt * QR;

    const char* Qh_g = (const char*)(g_qh + ((size_t)(b * HQ + h) * S_ + q0) * D_);
    const char* Ql_g = (const char*)(g_ql + ((size_t)(b * HQ + h) * S_ + q0) * D_);
    const char* Kh_g = (const char*)(g_kh + (size_t)(b * HKV + kvh) * S_ * D_);
    const char* Kl_g = (const char*)(g_kl + (size_t)(b * HKV + kvh) * S_ * D_);
    const char* Vh_g = (const char*)(g_vh + (size_t)(b * HKV + kvh) * S_ * D_);
    const char* Vl_g = (const char*)(g_vl + (size_t)(b * HKV + kvh) * S_ * D_);

    const int T = q0 / KT + 2;   // causal: KV tiles 0 .. q0/64+1

#define KVFILL(s, t) do {                                                   \
        uint32_t base = sb + 2 * QARR + (uint32_t)(s) * KVSTG;              \
        size_t gk = (size_t)(t) * KT * 256;                                 \
        _Pragma("unroll")                                                   \
        for (int c = 0; c < 4; ++c) {                                       \
            int idx = c * 256 + tid;                                        \
            int r = idx >> 4, o16 = (idx & 15) * 16;                        \
            uint32_t so = (uint32_t)(r * DSTR + o16);                       \
            size_t gb = gk + (size_t)r * 256 + o16;                         \
            CP16(base + so,            Kh_g + gb);                          \
            CP16(base + KARR + so,     Kl_g + gb);                          \
            CP16(base + 2 * KARR + so, Vh_g + gb);                          \
            CP16(base + 3 * KARR + so, Vl_g + gb);                          \
        }                                                                   \
    } while (0)

    // prologue: Q + first two KV tiles
    {
#pragma unroll
        for (int c = 0; c < 8; ++c) {
            int idx = c * 256 + tid;
            int r = idx >> 4, o16 = (idx & 15) * 16;
            uint32_t so = (uint32_t)(r * DSTR + o16);
            size_t gb = (size_t)r * 256 + o16;
            CP16(sb + so,        Qh_g + gb);
            CP16(sb + QARR + so, Ql_g + gb);
        }
        KVFILL(0, 0); CP_COMMIT();
        KVFILL(1, 1); CP_COMMIT();
    }

    const uint32_t a_off = (uint32_t)((lane & 15) * DSTR + (lane >> 4) * 16);
    const uint32_t b_off = (uint32_t)((lane & 7) * DSTR + ((lane >> 4) & 1) * (8 * DSTR)
                                      + ((lane >> 3) & 1) * 16);
    const uint32_t qbase = sb + (uint32_t)(wid * 16) * DSTR;

    float o[16][4];
#pragma unroll
    for (int j = 0; j < 16; ++j)
#pragma unroll
        for (int v = 0; v < 4; ++v) o[j][v] = 0.f;
    float mi[2] = {-1e30f, -1e30f};
    float li[2] = {0.f, 0.f};

    const float SC = 0.08838834764831845f * 1.4426950408889634f;  // scale * log2(e)

    for (int t = 0; t < T; ++t) {
        const int s = t & 1;
        if (t + 1 < T) CP_WAIT(1); else CP_WAIT(0);
        __syncthreads();

        const uint32_t kbase = sb + 2 * QARR + (uint32_t)s * KVSTG;
        const uint32_t vbase = kbase + 2 * KARR;

        // ---- S = Q K^T (bf16x3) ----
        float sc[8][4];
#pragma unroll
        for (int j = 0; j < 8; ++j)
#pragma unroll
            for (int v = 0; v < 4; ++v) sc[j][v] = 0.f;

#pragma unroll
        for (int kk = 0; kk < 8; ++kk) {
            uint32_t ah[4], al[4];
            uint32_t aa = qbase + a_off + kk * 32;
            LDMX4(ah, aa);
            LDMX4(al, aa + QARR);
#pragma unroll
            for (int p = 0; p < 4; ++p) {
                uint32_t kh[4], kl[4];
                uint32_t ba = kbase + (uint32_t)(p * 16) * DSTR + b_off + kk * 32;
                LDMX4(kh, ba);
                LDMX4(kl, ba + KARR);
                MMA16816(sc[2 * p],     ah, kh);
                MMA16816(sc[2 * p + 1], ah, kh + 2);
                MMA16816(sc[2 * p],     ah, kl);
                MMA16816(sc[2 * p + 1], ah, kl + 2);
                MMA16816(sc[2 * p],     al, kh);
                MMA16816(sc[2 * p + 1], al, kh + 2);
            }
        }

        // ---- scale (base-2) + causal mask ----
        const int k0 = t * KT;
        const bool tail = (t + 2 >= T);
#pragma unroll
        for (int tl = 0; tl < 8; ++tl)
#pragma unroll
            for (int v = 0; v < 4; ++v) {
                float x = sc[tl][v] * SC;
                if (tail) {
                    int col = k0 + tl * 8 + (lane & 3) * 2 + (v & 1);
                    int row = q0 + wid * 16 + (lane >> 2) + ((v >> 1) << 3);
                    if (col > row) x = -1e30f;
                }
                sc[tl][v] = x;
            }

        // ---- online softmax per row-half; pack P to bf16 hi/lo fragments ----
        uint32_t PH0[8], PH1[8], PL0[8], PL1[8];
#pragma unroll
        for (int hh = 0; hh < 2; ++hh) {
            float rm = -1e30f;
#pragma unroll
            for (int tl = 0; tl < 8; ++tl)
                rm = fmaxf(rm, fmaxf(sc[tl][2 * hh], sc[tl][2 * hh + 1]));
            rm = fmaxf(rm, __shfl_xor_sync(0xffffffffu, rm, 1));
            rm = fmaxf(rm, __shfl_xor_sync(0xffffffffu, rm, 2));
            float mnew = fmaxf(mi[hh], rm);
            float corr = fexp2(mi[hh] - mnew);
            float rs = 0.f;
#pragma unroll
            for (int tl = 0; tl < 8; ++tl) {
                float p0 = fexp2(sc[tl][2 * hh]     - mnew);
                float p1 = fexp2(sc[tl][2 * hh + 1] - mnew);
                rs += p0 + p1;
                __nv_bfloat16 b0 = __float2bfloat16(p0), b1 = __float2bfloat16(p1);
                __nv_bfloat162 hp(b0, b1);
                float l0 = p0 - __bfloat162float(b0);
                float l1 = p1 - __bfloat162float(b1);
                __nv_bfloat162 lp(__float2bfloat16(l0), __float2bfloat16(l1));
                if (hh == 0) { PH0[tl] = *(uint32_t*)&hp; PL0[tl] = *(uint32_t*)&lp; }
                else         { PH1[tl] = *(uint32_t*)&hp; PL1[tl] = *(uint32_t*)&lp; }
            }
            rs += __shfl_xor_sync(0xffffffffu, rs, 1);
            rs += __shfl_xor_sync(0xffffffffu, rs, 2);
            li[hh] = li[hh] * corr + rs;
            mi[hh] = mnew;
#pragma unroll
            for (int j = 0; j < 16; ++j) {
                o[j][2 * hh]     *= corr;
                o[j][2 * hh + 1] *= corr;
            }
        }

        // ---- O += P V (bf16x3, P fragments from registers, V via ldmatrix.trans) ----
#pragma unroll
        for (int kk2 = 0; kk2 < 4; ++kk2) {
            uint32_t ph[4] = {PH0[2 * kk2], PH1[2 * kk2], PH0[2 * kk2 + 1], PH1[2 * kk2 + 1]};
            uint32_t pl[4] = {PL0[2 * kk2], PL1[2 * kk2], PL0[2 * kk2 + 1], PL1[2 * kk2 + 1]};
#pragma unroll
            for (int p = 0; p < 8; ++p) {
                uint32_t vh[4], vl[4];
                uint32_t va = vbase + (uint32_t)(kk2 * 16) * DSTR + a_off + p * 32;
                LDMX4T(vh, va);
                LDMX4T(vl, va + KARR);
                MMA16816(o[2 * p],     ph, vh);
                MMA16816(o[2 * p + 1], ph, vh + 2);
                MMA16816(o[2 * p],     ph, vl);
                MMA16816(o[2 * p + 1], ph, vl + 2);
                MMA16816(o[2 * p],     pl, vh);
                MMA16816(o[2 * p + 1], pl, vh + 2);
            }
        }

        __syncthreads();
        if (t + 2 < T) { KVFILL(s, t + 2); CP_COMMIT(); }
    }

    // ---- epilogue: normalize, sigmoid-gate, bf16 hi/lo store ----
#pragma unroll
    for (int hh = 0; hh < 2; ++hh) {
        int row = q0 + wid * 16 + (lane >> 2) + hh * 8;
        size_t m = (size_t)b * S_ + row;
        float inv = 1.f / li[hh];
        const float* gr = gate + m * HID + h * D_;
        __nv_bfloat16* oh = g_at_hi + m * HID + h * D_;
        __nv_bfloat16* ol = g_at_lo + m * HID + h * D_;
#pragma unroll
        for (int j = 0; j < 16; ++j) {
            int d0 = j * 8 + (lane & 3) * 2;
            float2 gv = *(const float2*)(gr + d0);
            float s0 = 1.f / (1.f + fexp2(-gv.x * 1.4426950408889634f));
            float s1 = 1.f / (1.f + fexp2(-gv.y * 1.4426950408889634f));
            float v0 = o[j][2 * hh]     * inv * s0;
            float v1 = o[j][2 * hh + 1] * inv * s1;
            __nv_bfloat16 h0 = __float2bfloat16(v0), h1 = __float2bfloat16(v1);
            __nv_bfloat162 hp(h0, h1);
            __nv_bfloat162 lp(__float2bfloat16(v0 - __bfloat162float(h0)),
                              __float2bfloat16(v1 - __bfloat162float(h1)));
            *(__nv_bfloat162*)(oh + d0) = hp;
            *(__nv_bfloat162*)(ol + d0) = lp;
        }
    }
#undef KVFILL
}

// ---------------- launch ----------------
extern "C" void kernel_launch(void* const* d_in, const int* in_sizes, int n_in,
                              void* d_out, int out_size)
{
    const float* hs   = (const float*)d_in[0];
    const float* cosT = (const float*)d_in[1];
    const float* sinT = (const float*)d_in[2];
    const float* Wq   = (const float*)d_in[3];
    const float* Wk   = (const float*)d_in[4];
    const float* Wv   = (const float*)d_in[5];
    const float* Wg   = (const float*)d_in[6];
    const float* Wo   = (const float*)d_in[7];
    const float* qw   = (const float*)d_in[8];
    const float* kw   = (const float*)d_in[9];
    float* out = (float*)d_out;

    float *qp, *kp, *vp, *gp;
    cudaGetSymbolAddress((void**)&qp, g_qproj);
    cudaGetSymbolAddress((void**)&kp, g_kproj);
    cudaGetSymbolAddress((void**)&vp, g_vproj);
    cudaGetSymbolAddress((void**)&gp, g_gate);

    __nv_bfloat16 *hsh, *hsl, *wqh, *wql, *wkh, *wkl, *wvh, *wvl, *wgh, *wgl, *woh, *wol, *ath, *atl;
    cudaGetSymbolAddress((void**)&hsh, g_hs_hi); cudaGetSymbolAddress((void**)&hsl, g_hs_lo);
    cudaGetSymbolAddress((void**)&wqh, g_wq_hi); cudaGetSymbolAddress((void**)&wql, g_wq_lo);
    cudaGetSymbolAddress((void**)&wkh, g_wk_hi); cudaGetSymbolAddress((void**)&wkl, g_wk_lo);
    cudaGetSymbolAddress((void**)&wvh, g_wv_hi); cudaGetSymbolAddress((void**)&wvl, g_wv_lo);
    cudaGetSymbolAddress((void**)&wgh, g_wg_hi); cudaGetSymbolAddress((void**)&wgl, g_wg_lo);
    cudaGetSymbolAddress((void**)&woh, g_wo_hi); cudaGetSymbolAddress((void**)&wol, g_wo_lo);
    cudaGetSymbolAddress((void**)&ath, g_at_hi); cudaGetSymbolAddress((void**)&atl, g_at_lo);

    cudaFuncSetAttribute(gemm_bf16x3, cudaFuncAttributeMaxDynamicSharedMemorySize, GEMM_SMEM);
    cudaFuncSetAttribute(attn_tc, cudaFuncAttributeMaxDynamicSharedMemorySize, ATTN_SMEM);

    // fp32 -> bf16 hi/lo splits
    const int nHS = MROWS * HID, nSq = HID * HID, nKv = KVW * HID;
    split_bf16<<<nHS / 1024, 256>>>(hs, hsh, hsl, nHS);
    split_bf16<<<nSq / 1024, 256>>>(Wq, wqh, wql, nSq);
    split_bf16<<<nKv / 1024, 256>>>(Wk, wkh, wkl, nKv);
    split_bf16<<<nKv / 1024, 256>>>(Wv, wvh, wvl, nKv);
    split_bf16<<<nSq / 1024, 256>>>(Wg, wgh, wgl, nSq);
    split_bf16<<<nSq / 1024, 256>>>(Wo, woh, wol, nSq);

    // projections (tensor cores, bf16x3)
    gemm_bf16x3<<<dim3(HID / 128, MROWS / 128), 256, GEMM_SMEM>>>(hsh, hsl, wqh, wql, qp, HID, HID);
    gemm_bf16x3<<<dim3(KVW / 128, MROWS / 128), 256, GEMM_SMEM>>>(hsh, hsl, wkh, wkl, kp, KVW, HID);
    gemm_bf16x3<<<dim3(KVW / 128, MROWS / 128), 256, GEMM_SMEM>>>(hsh, hsl, wvh, wvl, vp, KVW, HID);
    gemm_bf16x3<<<dim3(HID / 128, MROWS / 128), 256, GEMM_SMEM>>>(hsh, hsl, wgh, wgl, gp, HID, HID);

    // RMSNorm + RoPE + transpose -> bf16 hi/lo q/k/v
    {
        int total_warps = MROWS * (HQ + 2 * HKV);
        rope_norm_kernel<<<total_warps / 8, 256>>>(cosT, sinT, qw, kw);
    }

    // tensor-core causal flash attention + gated epilogue
    attn_tc<<<dim3(S_ / QR, B_ * HQ), 256, ATTN_SMEM>>>(gp);

    // output projection (tensor cores)
    gemm_bf16x3<<<dim3(HID / 128, MROWS / 128), 256, GEMM_SMEM>>>(ath, atl, woh, wol, out, HID, HID);
}

// round 8
// speedup vs baseline: 3.2023x; 1.1486x over previous
#include <cuda_runtime.h>
#include <cuda_bf16.h>
#include <math.h>
#include <cstdint>

#define B_    2
#define S_    2048
#define HID   2048
#define HQ    16
#define HKV   4
#define D_    128
#define MROWS (B_ * S_)      // 4096
#define KVW   (HKV * D_)     // 512

// ---------------- scratch (allocation-free: __device__ globals) ----------------
__device__ float g_qproj[(size_t)MROWS * HID];
__device__ float g_kproj[(size_t)MROWS * KVW];
__device__ float g_vproj[(size_t)MROWS * KVW];
__device__ float g_gate [(size_t)MROWS * HID];

// q/k/v in bf16 hi/lo, [b][h][s][d]
__device__ __nv_bfloat16 g_qh[(size_t)B_ * HQ  * S_ * D_];
__device__ __nv_bfloat16 g_ql[(size_t)B_ * HQ  * S_ * D_];
__device__ __nv_bfloat16 g_kh[(size_t)B_ * HKV * S_ * D_];
__device__ __nv_bfloat16 g_kl[(size_t)B_ * HKV * S_ * D_];
__device__ __nv_bfloat16 g_vh[(size_t)B_ * HKV * S_ * D_];
__device__ __nv_bfloat16 g_vl[(size_t)B_ * HKV * S_ * D_];

// bf16 hi/lo splits for GEMMs
__device__ __nv_bfloat16 g_hs_hi[(size_t)MROWS * HID];
__device__ __nv_bfloat16 g_hs_lo[(size_t)MROWS * HID];
__device__ __nv_bfloat16 g_wq_hi[(size_t)HID * HID];
__device__ __nv_bfloat16 g_wq_lo[(size_t)HID * HID];
__device__ __nv_bfloat16 g_wk_hi[(size_t)KVW * HID];
__device__ __nv_bfloat16 g_wk_lo[(size_t)KVW * HID];
__device__ __nv_bfloat16 g_wv_hi[(size_t)KVW * HID];
__device__ __nv_bfloat16 g_wv_lo[(size_t)KVW * HID];
__device__ __nv_bfloat16 g_wg_hi[(size_t)HID * HID];
__device__ __nv_bfloat16 g_wg_lo[(size_t)HID * HID];
__device__ __nv_bfloat16 g_wo_hi[(size_t)HID * HID];
__device__ __nv_bfloat16 g_wo_lo[(size_t)HID * HID];
__device__ __nv_bfloat16 g_at_hi[(size_t)MROWS * HID];
__device__ __nv_bfloat16 g_at_lo[(size_t)MROWS * HID];

// ---------------- PTX helpers (base sm_100-safe) ----------------
__device__ __forceinline__ uint32_t smem_u32(const void* p) {
    return (uint32_t)__cvta_generic_to_shared(p);
}
#define CP16(dst, src) \
    asm volatile("cp.async.cg.shared.global [%0], [%1], 16;\n" :: "r"(dst), "l"(src))
#define CP_COMMIT() asm volatile("cp.async.commit_group;\n" ::: "memory")
#define CP_WAIT(n)  asm volatile("cp.async.wait_group %0;\n" :: "n"(n) : "memory")

#define LDMX4(r, addr) \
    asm volatile("ldmatrix.sync.aligned.m8n8.x4.shared.b16 {%0,%1,%2,%3}, [%4];" \
        : "=r"((r)[0]), "=r"((r)[1]), "=r"((r)[2]), "=r"((r)[3]) : "r"(addr))
#define LDMX4T(r, addr) \
    asm volatile("ldmatrix.sync.aligned.m8n8.x4.trans.shared.b16 {%0,%1,%2,%3}, [%4];" \
        : "=r"((r)[0]), "=r"((r)[1]), "=r"((r)[2]), "=r"((r)[3]) : "r"(addr))

#define MMA16816(d, a, b) \
    asm volatile("mma.sync.aligned.m16n8k16.row.col.f32.bf16.bf16.f32 " \
        "{%0,%1,%2,%3}, {%4,%5,%6,%7}, {%8,%9}, {%0,%1,%2,%3};" \
        : "+f"((d)[0]), "+f"((d)[1]), "+f"((d)[2]), "+f"((d)[3]) \
        : "r"((a)[0]), "r"((a)[1]), "r"((a)[2]), "r"((a)[3]), "r"((b)[0]), "r"((b)[1]))

__device__ __forceinline__ float fexp2(float x) {
    float y; asm("ex2.approx.ftz.f32 %0, %1;" : "=f"(y) : "f"(x)); return y;
}

// ---------------- split: fp32 -> (bf16 hi, bf16 lo) ----------------
__global__ void __launch_bounds__(256) split_bf16(const float* __restrict__ x,
                                                  __nv_bfloat16* __restrict__ hi,
                                                  __nv_bfloat16* __restrict__ lo, int n)
{
    int i = (blockIdx.x * blockDim.x + threadIdx.x) * 4;
    if (i >= n) return;
    float4 v = *(const float4*)(x + i);
    __nv_bfloat16 h0 = __float2bfloat16(v.x), h1 = __float2bfloat16(v.y);
    __nv_bfloat16 h2 = __float2bfloat16(v.z), h3 = __float2bfloat16(v.w);
    __nv_bfloat16 l0 = __float2bfloat16(v.x - __bfloat162float(h0));
    __nv_bfloat16 l1 = __float2bfloat16(v.y - __bfloat162float(h1));
    __nv_bfloat16 l2 = __float2bfloat16(v.z - __bfloat162float(h2));
    __nv_bfloat16 l3 = __float2bfloat16(v.w - __bfloat162float(h3));
    *(__nv_bfloat162*)(hi + i)     = __nv_bfloat162(h0, h1);
    *(__nv_bfloat162*)(hi + i + 2) = __nv_bfloat162(h2, h3);
    *(__nv_bfloat162*)(lo + i)     = __nv_bfloat162(l0, l1);
    *(__nv_bfloat162*)(lo + i + 2) = __nv_bfloat162(l2, l3);
}

// ---------------- mma.sync bf16x3 GEMM body: warp tile 64x64, CTA 128x128 ----------------
// 128 threads (4 warps, 2Mx2N), BK=32, rows padded to 80B, cp.async double buffer, 2 CTAs/SM.
#define BK     32
#define ROWB   80
#define OPB    (128 * ROWB)         // 10240
#define STG    (4 * OPB)            // 40960 (Ahi, Alo, Bhi, Blo)
#define GEMM_SMEM (2 * STG)         // 81920

__device__ __forceinline__ void gemm_body(
    const __nv_bfloat16* __restrict__ Ahi, const __nv_bfloat16* __restrict__ Alo,
    const __nv_bfloat16* __restrict__ Bhi, const __nv_bfloat16* __restrict__ Blo,
    float* __restrict__ C, int N, int K, int bm, int bn, char* smem)
{
    const uint32_t sb = smem_u32(smem);
    const int tid  = threadIdx.x;
    const int wid  = tid >> 5, lane = tid & 31;
    const int wm   = wid & 1;          // 2 warps in M: 64 rows each
    const int wn   = wid >> 1;         // 2 warps in N: 64 cols each

    const uint32_t a_off = (uint32_t)((lane & 15) * ROWB + (lane >> 4) * 16);
    const uint32_t b_off = (uint32_t)((lane & 7) * ROWB + ((lane >> 4) & 1) * (8 * ROWB)
                                      + ((lane >> 3) & 1) * 16);

    float acc[4][8][4];
#pragma unroll
    for (int i = 0; i < 4; ++i)
#pragma unroll
        for (int j = 0; j < 8; ++j)
#pragma unroll
            for (int v = 0; v < 4; ++v) acc[i][j][v] = 0.f;

    const int T = K / BK;

#define FILL(s, kt) do {                                                          \
        uint32_t base = sb + (uint32_t)(s) * STG;                                 \
        int k0 = (kt) * BK;                                                       \
        _Pragma("unroll")                                                         \
        for (int c = 0; c < 4; ++c) {                                             \
            int chunk = c * 128 + tid;                                            \
            int r = chunk >> 2, o16 = (chunk & 3) * 16;                           \
            uint32_t so = (uint32_t)(r * ROWB + o16);                             \
            const char* pah = (const char*)(Ahi + (size_t)(bm + r) * K + k0) + o16; \
            const char* pal = (const char*)(Alo + (size_t)(bm + r) * K + k0) + o16; \
            const char* pbh = (const char*)(Bhi + (size_t)(bn + r) * K + k0) + o16; \
            const char* pbl = (const char*)(Blo + (size_t)(bn + r) * K + k0) + o16; \
            CP16(base + so,           pah);                                       \
            CP16(base + OPB + so,     pal);                                       \
            CP16(base + 2 * OPB + so, pbh);                                       \
            CP16(base + 3 * OPB + so, pbl);                                       \
        }                                                                         \
    } while (0)

    FILL(0, 0); CP_COMMIT();

    for (int t = 0; t < T; ++t) {
        const int s = t & 1;
        if (t + 1 < T) { FILL(s ^ 1, t + 1); CP_COMMIT(); CP_WAIT(1); }
        else           { CP_WAIT(0); }
        __syncthreads();

        const uint32_t abase = sb + (uint32_t)s * STG + (uint32_t)(wm * 64) * ROWB;
        const uint32_t bbase = sb + (uint32_t)s * STG + 2 * OPB + (uint32_t)(wn * 64) * ROWB;

#pragma unroll
        for (int ks = 0; ks < 2; ++ks) {
            uint32_t ah[4][4], al[4][4];
#pragma unroll
            for (int mi = 0; mi < 4; ++mi) {
                uint32_t aa = abase + (uint32_t)(mi * 16) * ROWB + a_off + ks * 32;
                LDMX4(ah[mi], aa);
                LDMX4(al[mi], aa + OPB);
            }
#pragma unroll
            for (int p = 0; p < 4; ++p) {
                uint32_t bh[4], bl[4];
                uint32_t ba = bbase + (uint32_t)(p * 16) * ROWB + b_off + ks * 32;
                LDMX4(bh, ba);
                LDMX4(bl, ba + OPB);
#pragma unroll
                for (int mi = 0; mi < 4; ++mi) {
                    MMA16816(acc[mi][2 * p],     ah[mi], bh);
                    MMA16816(acc[mi][2 * p + 1], ah[mi], bh + 2);
                    MMA16816(acc[mi][2 * p],     ah[mi], bl);
                    MMA16816(acc[mi][2 * p + 1], ah[mi], bl + 2);
                    MMA16816(acc[mi][2 * p],     al[mi], bh);
                    MMA16816(acc[mi][2 * p + 1], al[mi], bh + 2);
                }
            }
        }
        __syncthreads();
    }

    const int r0 = bm + wm * 64 + (lane >> 2);
    const int c0 = bn + wn * 64 + (lane & 3) * 2;
#pragma unroll
    for (int mi = 0; mi < 4; ++mi)
#pragma unroll
        for (int ni = 0; ni < 8; ++ni) {
            int row = r0 + mi * 16;
            int col = c0 + ni * 8;
            *(float2*)(C + (size_t)row * N + col)       = make_float2(acc[mi][ni][0], acc[mi][ni][1]);
            *(float2*)(C + (size_t)(row + 8) * N + col) = make_float2(acc[mi][ni][2], acc[mi][ni][3]);
        }
#undef FILL
}

// fused Q/K/V/G projections: grid.x = 16(Q)+4(K)+4(V)+16(G) = 40, grid.y = 32
__global__ void __launch_bounds__(128, 2) gemm_qkvg()
{
    extern __shared__ char smem[];
    const int bx = blockIdx.x;
    const int bm = blockIdx.y * 128;
    const __nv_bfloat16 *Bh, *Bl;
    float* C;
    int N, bn;
    if (bx < 16)      { Bh = g_wq_hi; Bl = g_wq_lo; C = g_qproj; N = HID; bn = bx * 128; }
    else if (bx < 20) { Bh = g_wk_hi; Bl = g_wk_lo; C = g_kproj; N = KVW; bn = (bx - 16) * 128; }
    else if (bx < 24) { Bh = g_wv_hi; Bl = g_wv_lo; C = g_vproj; N = KVW; bn = (bx - 20) * 128; }
    else              { Bh = g_wg_hi; Bl = g_wg_lo; C = g_gate;  N = HID; bn = (bx - 24) * 128; }
    gemm_body(g_hs_hi, g_hs_lo, Bh, Bl, C, N, HID, bm, bn, smem);
}

// generic GEMM (used for the Wo projection)
__global__ void __launch_bounds__(128, 2)
gemm_bf16x3(const __nv_bfloat16* __restrict__ Ahi, const __nv_bfloat16* __restrict__ Alo,
            const __nv_bfloat16* __restrict__ Bhi, const __nv_bfloat16* __restrict__ Blo,
            float* __restrict__ C, int N, int K)
{
    extern __shared__ char smem[];
    gemm_body(Ahi, Alo, Bhi, Blo, C, N, K, blockIdx.y * 128, blockIdx.x * 128, smem);
}

// ---------------- fused RMSNorm + RoPE + transpose -> bf16 hi/lo ----------------
__device__ __forceinline__ void st_hilo(__nv_bfloat16* ph, __nv_bfloat16* pl, float v) {
    __nv_bfloat16 h = __float2bfloat16(v);
    *ph = h;
    *pl = __float2bfloat16(v - __bfloat162float(h));
}

__global__ void __launch_bounds__(256) rope_norm_kernel(const float* __restrict__ cosT,
                                                        const float* __restrict__ sinT,
                                                        const float* __restrict__ qw,
                                                        const float* __restrict__ kw)
{
    const int gw   = (blockIdx.x * blockDim.x + threadIdx.x) >> 5;
    const int lane = threadIdx.x & 31;
    const int NQ = MROWS * HQ;
    const int NK = MROWS * HKV;

    if (gw < NQ + NK) {
        bool isq = (gw < NQ);
        int idx = isq ? gw : gw - NQ;
        int nh  = isq ? HQ : HKV;
        int h = idx % nh;
        int m = idx / nh;
        int s = m % S_, b = m / S_;
        const float* x = (isq ? g_qproj + (size_t)m * HID : g_kproj + (size_t)m * KVW) + h * D_;
        const float* w = isq ? qw : kw;

        float x0 = x[lane], x1 = x[lane + 32], x2 = x[lane + 64], x3 = x[lane + 96];
        float ss = x0 * x0 + x1 * x1 + x2 * x2 + x3 * x3;
#pragma unroll
        for (int off = 16; off; off >>= 1) ss += __shfl_xor_sync(0xffffffffu, ss, off);
        float r = rsqrtf(ss * (1.f / 128.f) + 1e-6f);
        x0 = x0 * r * w[lane];
        x1 = x1 * r * w[lane + 32];
        x2 = x2 * r * w[lane + 64];
        x3 = x3 * r * w[lane + 96];

        const float* c  = cosT + (size_t)s * D_;
        const float* sn = sinT + (size_t)s * D_;
        float o0 = x0 * c[lane]      - x2 * sn[lane];
        float o1 = x1 * c[lane + 32] - x3 * sn[lane + 32];
        float o2 = x2 * c[lane + 64] + x0 * sn[lane + 64];
        float o3 = x3 * c[lane + 96] + x1 * sn[lane + 96];

        size_t base = isq ? (size_t)((b * HQ + h) * S_ + s) * D_
                          : (size_t)((b * HKV + h) * S_ + s) * D_;
        __nv_bfloat16* oh = isq ? g_qh + base : g_kh + base;
        __nv_bfloat16* ol = isq ? g_ql + base : g_kl + base;
        st_hilo(oh + lane,      ol + lane,      o0);
        st_hilo(oh + lane + 32, ol + lane + 32, o1);
        st_hilo(oh + lane + 64, ol + lane + 64, o2);
        st_hilo(oh + lane + 96, ol + lane + 96, o3);
    } else if (gw < NQ + 2 * NK) {
        int vi = gw - NQ - NK;
        int h = vi % HKV;
        int m = vi / HKV;
        int s = m % S_, b = m / S_;
        const float* x = g_vproj + (size_t)m * KVW + h * D_;
        size_t base = (size_t)((b * HKV + h) * S_ + s) * D_;
        st_hilo(g_vh + base + lane,      g_vl + base + lane,      x[lane]);
        st_hilo(g_vh + base + lane + 32, g_vl + base + lane + 32, x[lane + 32]);
        st_hilo(g_vh + base + lane + 64, g_vl + base + lane + 64, x[lane + 64]);
        st_hilo(g_vh + base + lane + 96, g_vl + base + lane + 96, x[lane + 96]);
    }
}

// ---------------- tensor-core flash attention (causal, bf16x3) ----------------
#define QR    128
#define KT    64
#define DSTR  272
#define QARR  (QR * DSTR)
#define KARR  (KT * DSTR)
#define KVSTG (4 * KARR)
#define ATTN_SMEM (2 * QARR + 2 * KVSTG)   // 208896

__global__ void __launch_bounds__(256) attn_tc(const float* __restrict__ gate)
{
    extern __shared__ char smc[];
    const uint32_t sb = smem_u32(smc);
    const int tid = threadIdx.x;
    const int wid = tid >> 5, lane = tid & 31;
    const int bh = blockIdx.y;
    const int b = bh >> 4, h = bh & 15;
    const int kvh = h >> 2;
    const int qt = gridDim.x - 1 - blockIdx.x;
    const int q0 = qt * QR;

    const char* Qh_g = (const char*)(g_qh + ((size_t)(b * HQ + h) * S_ + q0) * D_);
    const char* Ql_g = (const char*)(g_ql + ((size_t)(b * HQ + h) * S_ + q0) * D_);
    const char* Kh_g = (const char*)(g_kh + (size_t)(b * HKV + kvh) * S_ * D_);
    const char* Kl_g = (const char*)(g_kl + (size_t)(b * HKV + kvh) * S_ * D_);
    const char* Vh_g = (const char*)(g_vh + (size_t)(b * HKV + kvh) * S_ * D_);
    const char* Vl_g = (const char*)(g_vl + (size_t)(b * HKV + kvh) * S_ * D_);

    const int T = q0 / KT + 2;

#define KVFILL(s, t) do {                                                   \
        uint32_t base = sb + 2 * QARR + (uint32_t)(s) * KVSTG;              \
        size_t gk = (size_t)(t) * KT * 256;                                 \
        _Pragma("unroll")                                                   \
        for (int c = 0; c < 4; ++c) {                                       \
            int idx = c * 256 + tid;                                        \
            int r = idx >> 4, o16 = (idx & 15) * 16;                        \
            uint32_t so = (uint32_t)(r * DSTR + o16);                       \
            size_t gb = gk + (size_t)r * 256 + o16;                         \
            CP16(base + so,            Kh_g + gb);                          \
            CP16(base + KARR + so,     Kl_g + gb);                          \
            CP16(base + 2 * KARR + so, Vh_g + gb);                          \
            CP16(base + 3 * KARR + so, Vl_g + gb);                          \
        }                                                                   \
    } while (0)

    {
#pragma unroll
        for (int c = 0; c < 8; ++c) {
            int idx = c * 256 + tid;
            int r = idx >> 4, o16 = (idx & 15) * 16;
            uint32_t so = (uint32_t)(r * DSTR + o16);
            size_t gb = (size_t)r * 256 + o16;
            CP16(sb + so,        Qh_g + gb);
            CP16(sb + QARR + so, Ql_g + gb);
        }
        KVFILL(0, 0); CP_COMMIT();
        KVFILL(1, 1); CP_COMMIT();
    }

    const uint32_t a_off = (uint32_t)((lane & 15) * DSTR + (lane >> 4) * 16);
    const uint32_t b_off = (uint32_t)((lane & 7) * DSTR + ((lane >> 4) & 1) * (8 * DSTR)
                                      + ((lane >> 3) & 1) * 16);
    const uint32_t qbase = sb + (uint32_t)(wid * 16) * DSTR;

    float o[16][4];
#pragma unroll
    for (int j = 0; j < 16; ++j)
#pragma unroll
        for (int v = 0; v < 4; ++v) o[j][v] = 0.f;
    float mi[2] = {-1e30f, -1e30f};
    float li[2] = {0.f, 0.f};

    const float SC = 0.08838834764831845f * 1.4426950408889634f;

    for (int t = 0; t < T; ++t) {
        const int s = t & 1;
        if (t + 1 < T) CP_WAIT(1); else CP_WAIT(0);
        __syncthreads();

        const uint32_t kbase = sb + 2 * QARR + (uint32_t)s * KVSTG;
        const uint32_t vbase = kbase + 2 * KARR;

        float sc[8][4];
#pragma unroll
        for (int j = 0; j < 8; ++j)
#pragma unroll
            for (int v = 0; v < 4; ++v) sc[j][v] = 0.f;

#pragma unroll
        for (int kk = 0; kk < 8; ++kk) {
            uint32_t ah[4], al[4];
            uint32_t aa = qbase + a_off + kk * 32;
            LDMX4(ah, aa);
            LDMX4(al, aa + QARR);
#pragma unroll
            for (int p = 0; p < 4; ++p) {
                uint32_t kh[4], kl[4];
                uint32_t ba = kbase + (uint32_t)(p * 16) * DSTR + b_off + kk * 32;
                LDMX4(kh, ba);
                LDMX4(kl, ba + KARR);
                MMA16816(sc[2 * p],     ah, kh);
                MMA16816(sc[2 * p + 1], ah, kh + 2);
                MMA16816(sc[2 * p],     ah, kl);
                MMA16816(sc[2 * p + 1], ah, kl + 2);
                MMA16816(sc[2 * p],     al, kh);
                MMA16816(sc[2 * p + 1], al, kh + 2);
            }
        }

        const int k0 = t * KT;
        const bool tail = (t + 2 >= T);
#pragma unroll
        for (int tl = 0; tl < 8; ++tl)
#pragma unroll
            for (int v = 0; v < 4; ++v) {
                float x = sc[tl][v] * SC;
                if (tail) {
                    int col = k0 + tl * 8 + (lane & 3) * 2 + (v & 1);
                    int row = q0 + wid * 16 + (lane >> 2) + ((v >> 1) << 3);
                    if (col > row) x = -1e30f;
                }
                sc[tl][v] = x;
            }

        uint32_t PH0[8], PH1[8], PL0[8], PL1[8];
#pragma unroll
        for (int hh = 0; hh < 2; ++hh) {
            float rm = -1e30f;
#pragma unroll
            for (int tl = 0; tl < 8; ++tl)
                rm = fmaxf(rm, fmaxf(sc[tl][2 * hh], sc[tl][2 * hh + 1]));
            rm = fmaxf(rm, __shfl_xor_sync(0xffffffffu, rm, 1));
            rm = fmaxf(rm, __shfl_xor_sync(0xffffffffu, rm, 2));
            float mnew = fmaxf(mi[hh], rm);
            float corr = fexp2(mi[hh] - mnew);
            float rs = 0.f;
#pragma unroll
            for (int tl = 0; tl < 8; ++tl) {
                float p0 = fexp2(sc[tl][2 * hh]     - mnew);
                float p1 = fexp2(sc[tl][2 * hh + 1] - mnew);
                rs += p0 + p1;
                __nv_bfloat16 b0 = __float2bfloat16(p0), b1 = __float2bfloat16(p1);
                __nv_bfloat162 hp(b0, b1);
                float l0 = p0 - __bfloat162float(b0);
                float l1 = p1 - __bfloat162float(b1);
                __nv_bfloat162 lp(__float2bfloat16(l0), __float2bfloat16(l1));
                if (hh == 0) { PH0[tl] = *(uint32_t*)&hp; PL0[tl] = *(uint32_t*)&lp; }
                else         { PH1[tl] = *(uint32_t*)&hp; PL1[tl] = *(uint32_t*)&lp; }
            }
            rs += __shfl_xor_sync(0xffffffffu, rs, 1);
            rs += __shfl_xor_sync(0xffffffffu, rs, 2);
            li[hh] = li[hh] * corr + rs;
            mi[hh] = mnew;
#pragma unroll
            for (int j = 0; j < 16; ++j) {
                o[j][2 * hh]     *= corr;
                o[j][2 * hh + 1] *= corr;
            }
        }

#pragma unroll
        for (int kk2 = 0; kk2 < 4; ++kk2) {
            uint32_t ph[4] = {PH0[2 * kk2], PH1[2 * kk2], PH0[2 * kk2 + 1], PH1[2 * kk2 + 1]};
            uint32_t pl[4] = {PL0[2 * kk2], PL1[2 * kk2], PL0[2 * kk2 + 1], PL1[2 * kk2 + 1]};
#pragma unroll
            for (int p = 0; p < 8; ++p) {
                uint32_t vh[4], vl[4];
                uint32_t va = vbase + (uint32_t)(kk2 * 16) * DSTR + a_off + p * 32;
                LDMX4T(vh, va);
                LDMX4T(vl, va + KARR);
                MMA16816(o[2 * p],     ph, vh);
                MMA16816(o[2 * p + 1], ph, vh + 2);
                MMA16816(o[2 * p],     ph, vl);
                MMA16816(o[2 * p + 1], ph, vl + 2);
                MMA16816(o[2 * p],     pl, vh);
                MMA16816(o[2 * p + 1], pl, vh + 2);
            }
        }

        __syncthreads();
        if (t + 2 < T) { KVFILL(s, t + 2); CP_COMMIT(); }
    }

#pragma unroll
    for (int hh = 0; hh < 2; ++hh) {
        int row = q0 + wid * 16 + (lane >> 2) + hh * 8;
        size_t m = (size_t)b * S_ + row;
        float inv = 1.f / li[hh];
        const float* gr = gate + m * HID + h * D_;
        __nv_bfloat16* oh = g_at_hi + m * HID + h * D_;
        __nv_bfloat16* ol = g_at_lo + m * HID + h * D_;
#pragma unroll
        for (int j = 0; j < 16; ++j) {
            int d0 = j * 8 + (lane & 3) * 2;
            float2 gv = *(const float2*)(gr + d0);
            float s0 = 1.f / (1.f + fexp2(-gv.x * 1.4426950408889634f));
            float s1 = 1.f / (1.f + fexp2(-gv.y * 1.4426950408889634f));
            float v0 = o[j][2 * hh]     * inv * s0;
            float v1 = o[j][2 * hh + 1] * inv * s1;
            __nv_bfloat16 h0 = __float2bfloat16(v0), h1 = __float2bfloat16(v1);
            __nv_bfloat162 hp(h0, h1);
            __nv_bfloat162 lp(__float2bfloat16(v0 - __bfloat162float(h0)),
                              __float2bfloat16(v1 - __bfloat162float(h1)));
            *(__nv_bfloat162*)(oh + d0) = hp;
            *(__nv_bfloat162*)(ol + d0) = lp;
        }
    }
#undef KVFILL
}

// ---------------- launch ----------------
extern "C" void kernel_launch(void* const* d_in, const int* in_sizes, int n_in,
                              void* d_out, int out_size)
{
    const float* hs   = (const float*)d_in[0];
    const float* cosT = (const float*)d_in[1];
    const float* sinT = (const float*)d_in[2];
    const float* Wq   = (const float*)d_in[3];
    const float* Wk   = (const float*)d_in[4];
    const float* Wv   = (const float*)d_in[5];
    const float* Wg   = (const float*)d_in[6];
    const float* Wo   = (const float*)d_in[7];
    const float* qw   = (const float*)d_in[8];
    const float* kw   = (const float*)d_in[9];
    float* out = (float*)d_out;

    float* gp;
    cudaGetSymbolAddress((void**)&gp, g_gate);

    __nv_bfloat16 *hsh, *hsl, *wqh, *wql, *wkh, *wkl, *wvh, *wvl, *wgh, *wgl, *woh, *wol, *ath, *atl;
    cudaGetSymbolAddress((void**)&hsh, g_hs_hi); cudaGetSymbolAddress((void**)&hsl, g_hs_lo);
    cudaGetSymbolAddress((void**)&wqh, g_wq_hi); cudaGetSymbolAddress((void**)&wql, g_wq_lo);
    cudaGetSymbolAddress((void**)&wkh, g_wk_hi); cudaGetSymbolAddress((void**)&wkl, g_wk_lo);
    cudaGetSymbolAddress((void**)&wvh, g_wv_hi); cudaGetSymbolAddress((void**)&wvl, g_wv_lo);
    cudaGetSymbolAddress((void**)&wgh, g_wg_hi); cudaGetSymbolAddress((void**)&wgl, g_wg_lo);
    cudaGetSymbolAddress((void**)&woh, g_wo_hi); cudaGetSymbolAddress((void**)&wol, g_wo_lo);
    cudaGetSymbolAddress((void**)&ath, g_at_hi); cudaGetSymbolAddress((void**)&atl, g_at_lo);

    cudaFuncSetAttribute(gemm_qkvg,   cudaFuncAttributeMaxDynamicSharedMemorySize, GEMM_SMEM);
    cudaFuncSetAttribute(gemm_bf16x3, cudaFuncAttributeMaxDynamicSharedMemorySize, GEMM_SMEM);
    cudaFuncSetAttribute(attn_tc,     cudaFuncAttributeMaxDynamicSharedMemorySize, ATTN_SMEM);

    // fp32 -> bf16 hi/lo splits
    const int nHS = MROWS * HID, nSq = HID * HID, nKv = KVW * HID;
    split_bf16<<<nHS / 1024, 256>>>(hs, hsh, hsl, nHS);
    split_bf16<<<nSq / 1024, 256>>>(Wq, wqh, wql, nSq);
    split_bf16<<<nKv / 1024, 256>>>(Wk, wkh, wkl, nKv);
    split_bf16<<<nKv / 1024, 256>>>(Wv, wvh, wvl, nKv);
    split_bf16<<<nSq / 1024, 256>>>(Wg, wgh, wgl, nSq);
    split_bf16<<<nSq / 1024, 256>>>(Wo, woh, wol, nSq);

    // fused Q/K/V/G projections (tensor cores, bf16x3, 64x64 warp tiles)
    gemm_qkvg<<<dim3(40, MROWS / 128), 128, GEMM_SMEM>>>();

    // RMSNorm + RoPE + transpose -> bf16 hi/lo q/k/v
    {
        int total_warps = MROWS * (HQ + 2 * HKV);
        rope_norm_kernel<<<total_warps / 8, 256>>>(cosT, sinT, qw, kw);
    }

    // tensor-core causal flash attention + gated epilogue
    attn_tc<<<dim3(S_ / QR, B_ * HQ), 256, ATTN_SMEM>>>(gp);

    // output projection (tensor cores)
    gemm_bf16x3<<<dim3(HID / 128, MROWS / 128), 128, GEMM_SMEM>>>(ath, atl, woh, wol, out, HID, HID);
}